// round 6
// baseline (speedup 1.0000x reference)
#include <cuda_runtime.h>
#include <cuda_bf16.h>
#include <math.h>

// Problem constants (fixed by the dataset): B=64 graphs, N=512 nodes/graph, C=256.
#define FULLMASK 0xffffffffu

// Scratch (device globals; no allocation allowed).
__device__ float ybuf[32768 * 256];      // cached mlp(h_new) per global row (32 MB)
__device__ float hnew_buf[64 * 256];     // h_new of current node, per graph
__device__ float tbuf[64 * 256];         // mlp layer-1 activations, per graph
__device__ unsigned gcnt[8 * 32];        // per-group barrier counters (padded)
__device__ unsigned ggen[8 * 32];        // per-group barrier generations (padded)

// 16-CTA group barrier (sense-reversing via generation counter). All 128 CTAs
// are co-resident (1 CTA/SM, 128 <= 148 SMs), so spinning is deadlock-free.
__device__ __forceinline__ void group_barrier(int gb) {
    __syncthreads();
    if (threadIdx.x == 0) {
        volatile unsigned* genp = (volatile unsigned*)&ggen[gb * 32];
        unsigned g = *genp;
        __threadfence();
        unsigned a = atomicAdd(&gcnt[gb * 32], 1u);
        if (a == 15u) {
            gcnt[gb * 32] = 0u;   // safe: all 16 arrived; none re-arrive before gen bump
            __threadfence();
            *genp = g + 1u;
        } else {
            while (*genp == g) { }
            __threadfence();
        }
    }
    __syncthreads();
}

// smem layout (floats): wih[48*256] whh[48*256] w1[16*256] w2[16*256]
//                       xsa[8*256] xsh[8*256] gis[48*8] ghs[48*8]
//                       bih[48] bhh[48] b1[16] b2[16]   -> 37760 floats = 151040 B
#define SMEM_FLOATS 37760
#define SMEM_BYTES  (SMEM_FLOATS * 4)

__global__ void __launch_bounds__(256, 1)
gnn_kernel(float* __restrict__ hx,
           const float* __restrict__ W1, const float* __restrict__ b1,
           const float* __restrict__ W2, const float* __restrict__ b2,
           const float* __restrict__ w_ih, const float* __restrict__ b_ih,
           const float* __restrict__ w_hh, const float* __restrict__ b_hh,
           const int* __restrict__ src_f, const int* __restrict__ gid_f,
           const float* __restrict__ msk_f,
           const int* __restrict__ src_b, const int* __restrict__ gid_b,
           const float* __restrict__ msk_b,
           int Kf, int Kb)
{
    extern __shared__ float sm[];
    float* wih = sm;                 // 48x256
    float* whh = wih + 12288;        // 48x256
    float* w1s = whh + 12288;        // 16x256
    float* w2s = w1s + 4096;         // 16x256
    float* xsa = w2s + 4096;         // 8x256 (agg rows; reused for t rows in M2)
    float* xsh = xsa + 2048;         // 8x256 (h rows; reused for h_new rows in M1)
    float* gis = xsh + 2048;         // 48x8
    float* ghs = gis + 384;          // 48x8
    float* bihs = ghs + 384;         // 48
    float* bhhs = bihs + 48;         // 48
    float* b1s = bhhs + 48;          // 16
    float* b2s = b1s + 16;           // 16

    const int tid  = threadIdx.x;
    const int lane = tid & 31;
    const int wrp  = tid >> 5;
    const int gb = blockIdx.x >> 4;      // graph group [0,8): graphs [8gb, 8gb+8)
    const int cb = blockIdx.x & 15;      // channel block [0,16): channels [16cb, 16cb+16)
    const int g0 = gb * 8;
    const int ch0 = cb * 16;

    // ---- load weight slices into smem (once) ----
    for (int idx = tid; idx < 48 * 256; idx += 256) {
        int lr = idx >> 8, k = idx & 255;                 // lr = gate*16 + c
        int grow = (lr >> 4) * 256 + ch0 + (lr & 15);
        wih[idx] = w_ih[grow * 256 + k];
        whh[idx] = w_hh[grow * 256 + k];
    }
    for (int idx = tid; idx < 16 * 256; idx += 256) {
        int r = idx >> 8, k = idx & 255;
        w1s[idx] = W1[(ch0 + r) * 256 + k];
        w2s[idx] = W2[(ch0 + r) * 256 + k];
    }
    if (tid < 48) {
        bihs[tid] = b_ih[(tid >> 4) * 256 + ch0 + (tid & 15)];
        bhhs[tid] = b_hh[(tid >> 4) * 256 + ch0 + (tid & 15)];
    }
    if (tid < 16) { b1s[tid] = b1[ch0 + tid]; b2s[tid] = b2[ch0 + tid]; }
    __syncthreads();

    for (int scan = 0; scan < 2; ++scan) {
        const int*   srcA = scan ? src_b : src_f;
        const int*   gidA = scan ? gid_b : gid_f;
        const float* mskA = scan ? msk_b : msk_f;
        const int K = scan ? Kb : Kf;

        for (int step = 0; step < 512; ++step) {
            const int n = scan ? (511 - step) : step;     // node id
            // ================= Phase G: gather agg + load h =================
            {
                const int gw = g0 + wrp;                  // this warp's graph
                const size_t eoff = (size_t)step * (size_t)K;
                float ar[8];
                #pragma unroll
                for (int j = 0; j < 8; j++) ar[j] = 0.f;
                for (int e0 = 0; e0 < K; e0 += 32) {
                    int e = e0 + lane;
                    int gd = -1, sv = 0; float mv = 0.f;
                    if (e < K) { gd = gidA[eoff + e]; mv = mskA[eoff + e]; sv = srcA[eoff + e]; }
                    unsigned bal = __ballot_sync(FULLMASK, (gd == gw) && (mv != 0.f));
                    while (bal) {
                        int l2 = __ffs(bal) - 1; bal &= bal - 1;
                        int   s  = __shfl_sync(FULLMASK, sv, l2);
                        float mm = __shfl_sync(FULLMASK, mv, l2);
                        const float* yr = ybuf + (size_t)s * 256;
                        #pragma unroll
                        for (int j = 0; j < 8; j++)
                            ar[j] = fmaf(mm, __ldcg(yr + lane + 32 * j), ar[j]);
                    }
                }
                #pragma unroll
                for (int j = 0; j < 8; j++) xsa[wrp * 256 + lane + 32 * j] = ar[j];
                const float* hr = hx + ((size_t)gw * 512 + n) * 256;
                #pragma unroll
                for (int j = 0; j < 8; j++)
                    xsh[wrp * 256 + lane + 32 * j] = __ldcg(hr + lane + 32 * j);
            }
            __syncthreads();

            // ================= Phase G: GEMM gi/gh (48 rows x 8 graphs each) =====
            {
                const bool ih = (wrp < 4);
                const float* wm = ih ? wih : whh;
                const float* xv = ih ? xsa : xsh;
                const int rb = (ih ? wrp : wrp - 4) * 12;
                float acc[12][8];
                #pragma unroll
                for (int i = 0; i < 12; i++)
                    #pragma unroll
                    for (int g = 0; g < 8; g++) acc[i][g] = 0.f;
                #pragma unroll
                for (int ki = 0; ki < 8; ki++) {
                    int kk = ki * 32 + lane;
                    float xa[8];
                    #pragma unroll
                    for (int g = 0; g < 8; g++) xa[g] = xv[g * 256 + kk];
                    #pragma unroll
                    for (int i = 0; i < 12; i++) {
                        float wv = wm[(rb + i) * 256 + kk];
                        #pragma unroll
                        for (int g = 0; g < 8; g++) acc[i][g] = fmaf(wv, xa[g], acc[i][g]);
                    }
                }
                #pragma unroll
                for (int off = 16; off >= 1; off >>= 1)
                    #pragma unroll
                    for (int i = 0; i < 12; i++)
                        #pragma unroll
                        for (int g = 0; g < 8; g++)
                            acc[i][g] += __shfl_xor_sync(FULLMASK, acc[i][g], off);
                float* ob = ih ? gis : ghs;
                #pragma unroll
                for (int i = 0; i < 12; i++)
                    #pragma unroll
                    for (int g = 0; g < 8; g++) {
                        int idx = i * 8 + g;
                        if (lane == (idx & 31)) ob[(rb + i) * 8 + g] = acc[i][g];
                    }
            }
            __syncthreads();

            // ================= Phase G: gate combine -> h_new ====================
            if (tid < 128) {
                int g = tid >> 4, c = tid & 15;
                float ir  = gis[c * 8 + g]        + bihs[c];
                float hrv = ghs[c * 8 + g]        + bhhs[c];
                float iz  = gis[(16 + c) * 8 + g] + bihs[16 + c];
                float hz  = ghs[(16 + c) * 8 + g] + bhhs[16 + c];
                float in_ = gis[(32 + c) * 8 + g] + bihs[32 + c];
                float hn  = ghs[(32 + c) * 8 + g] + bhhs[32 + c];
                float r = 1.f / (1.f + expf(-(ir + hrv)));
                float z = 1.f / (1.f + expf(-(iz + hz)));
                float nn = tanhf(in_ + r * hn);
                float ho = xsh[g * 256 + ch0 + c];
                float hv = (1.f - z) * nn + z * ho;
                __stcg(&hnew_buf[(g0 + g) * 256 + ch0 + c], hv);
            }
            group_barrier(gb);   // h_new complete across the group

            // ================= Phase M1: t = relu(W1 h_new + b1) =================
            {
                const float* hb = hnew_buf + (size_t)(g0 + wrp) * 256;
                #pragma unroll
                for (int j = 0; j < 8; j++)
                    xsh[wrp * 256 + lane + 32 * j] = __ldcg(hb + lane + 32 * j);
            }
            __syncthreads();
            if (tid < 128) {     // commit h_new into hx (safe: all G reads done)
                int g = tid >> 4, c = tid & 15;
                __stcg(&hx[((size_t)(g0 + g) * 512 + n) * 256 + ch0 + c],
                       xsh[g * 256 + ch0 + c]);
            }
            {
                float acc[2][8];
                #pragma unroll
                for (int i = 0; i < 2; i++)
                    #pragma unroll
                    for (int g = 0; g < 8; g++) acc[i][g] = 0.f;
                #pragma unroll
                for (int ki = 0; ki < 8; ki++) {
                    int kk = ki * 32 + lane;
                    float xa[8];
                    #pragma unroll
                    for (int g = 0; g < 8; g++) xa[g] = xsh[g * 256 + kk];
                    #pragma unroll
                    for (int i = 0; i < 2; i++) {
                        float wv = w1s[(wrp * 2 + i) * 256 + kk];
                        #pragma unroll
                        for (int g = 0; g < 8; g++) acc[i][g] = fmaf(wv, xa[g], acc[i][g]);
                    }
                }
                #pragma unroll
                for (int off = 16; off >= 1; off >>= 1)
                    #pragma unroll
                    for (int i = 0; i < 2; i++)
                        #pragma unroll
                        for (int g = 0; g < 8; g++)
                            acc[i][g] += __shfl_xor_sync(FULLMASK, acc[i][g], off);
                #pragma unroll
                for (int i = 0; i < 2; i++)
                    #pragma unroll
                    for (int g = 0; g < 8; g++) {
                        int idx = i * 8 + g;
                        if (lane == idx) {
                            float v = fmaxf(acc[i][g] + b1s[wrp * 2 + i], 0.f);
                            __stcg(&tbuf[(g0 + g) * 256 + ch0 + wrp * 2 + i], v);
                        }
                    }
            }
            group_barrier(gb);   // t complete across the group

            // ================= Phase M2: y = relu(W2 t + b2) =====================
            {
                const float* tb = tbuf + (size_t)(g0 + wrp) * 256;
                #pragma unroll
                for (int j = 0; j < 8; j++)
                    xsa[wrp * 256 + lane + 32 * j] = __ldcg(tb + lane + 32 * j);
            }
            __syncthreads();
            {
                float acc[2][8];
                #pragma unroll
                for (int i = 0; i < 2; i++)
                    #pragma unroll
                    for (int g = 0; g < 8; g++) acc[i][g] = 0.f;
                #pragma unroll
                for (int ki = 0; ki < 8; ki++) {
                    int kk = ki * 32 + lane;
                    float xa[8];
                    #pragma unroll
                    for (int g = 0; g < 8; g++) xa[g] = xsa[g * 256 + kk];
                    #pragma unroll
                    for (int i = 0; i < 2; i++) {
                        float wv = w2s[(wrp * 2 + i) * 256 + kk];
                        #pragma unroll
                        for (int g = 0; g < 8; g++) acc[i][g] = fmaf(wv, xa[g], acc[i][g]);
                    }
                }
                #pragma unroll
                for (int off = 16; off >= 1; off >>= 1)
                    #pragma unroll
                    for (int i = 0; i < 2; i++)
                        #pragma unroll
                        for (int g = 0; g < 8; g++)
                            acc[i][g] += __shfl_xor_sync(FULLMASK, acc[i][g], off);
                #pragma unroll
                for (int i = 0; i < 2; i++)
                    #pragma unroll
                    for (int g = 0; g < 8; g++) {
                        int idx = i * 8 + g;
                        if (lane == idx) {
                            float v = fmaxf(acc[i][g] + b2s[wrp * 2 + i], 0.f);
                            __stcg(&ybuf[((size_t)(g0 + g) * 512 + n) * 256 + ch0 + wrp * 2 + i], v);
                        }
                    }
            }
            group_barrier(gb);   // y complete -> next step may gather
        }
    }
}

extern "C" void kernel_launch(void* const* d_in, const int* in_sizes, int n_in,
                              void* d_out, int out_size) {
    const float* x    = (const float*)d_in[0];
    const float* W1   = (const float*)d_in[1];
    const float* b1   = (const float*)d_in[2];
    const float* W2   = (const float*)d_in[3];
    const float* b2   = (const float*)d_in[4];
    const float* w_ih = (const float*)d_in[5];
    const float* b_ih = (const float*)d_in[6];
    const float* w_hh = (const float*)d_in[7];
    const float* b_hh = (const float*)d_in[8];
    const int*   src_f = (const int*)d_in[9];
    const int*   gid_f = (const int*)d_in[10];
    const float* msk_f = (const float*)d_in[11];
    const int*   src_b = (const int*)d_in[12];
    const int*   gid_b = (const int*)d_in[13];
    const float* msk_b = (const float*)d_in[14];
    float* hx = (float*)d_out;

    int Kf = in_sizes[9] / 512;
    int Kb = in_sizes[12] / 512;

    // hx <- x (stream-ordered, precedes the kernel)
    cudaMemcpyAsync(hx, x, (size_t)32768 * 256 * sizeof(float),
                    cudaMemcpyDeviceToDevice);

    cudaFuncSetAttribute(gnn_kernel, cudaFuncAttributeMaxDynamicSharedMemorySize,
                         SMEM_BYTES);
    gnn_kernel<<<128, 256, SMEM_BYTES>>>(hx, W1, b1, W2, b2, w_ih, b_ih, w_hh, b_hh,
                                         src_f, gid_f, msk_f, src_b, gid_b, msk_b,
                                         Kf, Kb);
}

// round 7
// speedup vs baseline: 1.9129x; 1.9129x over previous
#include <cuda_runtime.h>
#include <cuda_bf16.h>
#include <math.h>

// B=64 graphs, N=512 nodes/graph, C=256 channels. 8 graph-groups x 16 channel-CTAs.
#define FULLMASK 0xffffffffu
#define MAXE 48

// Scratch (device globals; allocation is forbidden).
__device__ float ybuf[32768 * 256];      // cached mlp(h) per global row
__device__ float hnew_buf[64 * 256];     // h_new of current node per graph
__device__ float tbuf[64 * 256];         // MLP layer-1 activations per graph
__device__ unsigned gcnt[8 * 32];        // per-group barrier counters (padded)
__device__ unsigned ggen[8 * 32];        // per-group barrier generations (padded)

// 16-CTA sense-reversing group barrier (all 128 CTAs co-resident: 1 CTA/SM).
__device__ __forceinline__ void group_barrier(int gb) {
    __syncthreads();
    if (threadIdx.x == 0) {
        volatile unsigned* genp = (volatile unsigned*)&ggen[gb * 32];
        unsigned g = *genp;
        __threadfence();
        unsigned a = atomicAdd(&gcnt[gb * 32], 1u);
        if (a == 15u) {
            gcnt[gb * 32] = 0u;
            __threadfence();
            *genp = g + 1u;
        } else {
            while (*genp == g) { }
            __threadfence();
        }
    }
    __syncthreads();
}

// k-chunk interleave: chunk kc (0..63) stored at slot (kc%16)*4 + kc/16 so the
// 4 ks-split chunks used by one warp instruction are bank-consecutive.
__device__ __forceinline__ int xslot(int kc) { return ((kc & 15) << 2) + (kc >> 4); }

// smem float4 offsets
#define O_WG4  0            // 96*64   GRU rows (0-47 ih, 48-95 hh), interleaved
#define O_W14  6144         // 16*64
#define O_W24  7168         // 16*64
#define O_XSA  8192         // 8*68    agg (stride 68 float4)
#define O_XSH  8736         // 8*68    h / h_new / (stage)
// float offsets (from float 37120 = 9280 float4)
#define F_GIS  37120        // 48*8
#define F_GHS  37504        // 48*8
#define F_HST  37888        // 128
#define F_TST  38016        // 128
#define F_YST  38144        // 128
#define F_BIH  38272        // 48
#define F_BHH  38320        // 48
#define F_B1   38368        // 16
#define F_B2   38384        // 16
#define F_INT  38400        // int region: eg_src 8*48, eg_cnt 8
#define SMEM_FLOATS (38400 + 392)
#define SMEM_BYTES  (SMEM_FLOATS * 4)

__device__ __forceinline__ float4 f4add(float4 a, float4 b) {
    a.x += b.x; a.y += b.y; a.z += b.z; a.w += b.w; return a;
}

__global__ void __launch_bounds__(512, 1)
gnn_kernel(float* __restrict__ hx,
           const float* __restrict__ W1, const float* __restrict__ b1,
           const float* __restrict__ W2, const float* __restrict__ b2,
           const float* __restrict__ w_ih, const float* __restrict__ b_ih,
           const float* __restrict__ w_hh, const float* __restrict__ b_hh,
           const int* __restrict__ src_f, const int* __restrict__ gid_f,
           const float* __restrict__ msk_f,
           const int* __restrict__ src_b, const int* __restrict__ gid_b,
           const float* __restrict__ msk_b,
           int Kf, int Kb)
{
    extern __shared__ float4 sm4[];
    float* smf = (float*)sm4;
    int*   smi = (int*)(smf + F_INT);
    int*   eg_src = smi;                 // 8*MAXE
    int*   eg_cnt = smi + 8 * MAXE;      // 8

    const int tid  = threadIdx.x;
    const int lane = tid & 31;
    const int wid  = tid >> 5;
    const int gb   = blockIdx.x >> 4;    // graph group: graphs [8gb, 8gb+8)
    const int cb   = blockIdx.x & 15;    // channel block: channels [16cb, 16cb+16)
    const int g0   = gb * 8;
    const int ch0  = cb * 16;
    const int ks   = lane >> 3;          // k-split 0..3 (64 k each)
    const int gg   = lane & 7;           // graph within group

    // ---- stage weights into smem (once), k-chunk interleaved ----
    for (int idx = tid; idx < 96 * 64; idx += 512) {
        int row = idx >> 6, kc = idx & 63;
        const float* grow;
        if (row < 48) grow = w_ih + ((size_t)((row >> 4) * 256 + ch0 + (row & 15))) * 256;
        else { int r = row - 48;
               grow = w_hh + ((size_t)((r >> 4) * 256 + ch0 + (r & 15))) * 256; }
        sm4[O_WG4 + row * 64 + xslot(kc)] = *(const float4*)(grow + kc * 4);
    }
    for (int idx = tid; idx < 16 * 64; idx += 512) {
        int row = idx >> 6, kc = idx & 63;
        sm4[O_W14 + row * 64 + xslot(kc)] =
            *(const float4*)(W1 + (size_t)(ch0 + row) * 256 + kc * 4);
        sm4[O_W24 + row * 64 + xslot(kc)] =
            *(const float4*)(W2 + (size_t)(ch0 + row) * 256 + kc * 4);
    }
    if (tid < 48) {
        smf[F_BIH + tid] = b_ih[(tid >> 4) * 256 + ch0 + (tid & 15)];
        smf[F_BHH + tid] = b_hh[(tid >> 4) * 256 + ch0 + (tid & 15)];
    }
    if (tid < 16) { smf[F_B1 + tid] = b1[ch0 + tid]; smf[F_B2 + tid] = b2[ch0 + tid]; }
    __syncthreads();

    for (int scan = 0; scan < 2; ++scan) {
        const int*   srcA = scan ? src_b : src_f;
        const int*   gidA = scan ? gid_b : gid_f;
        const float* mskA = scan ? msk_b : msk_f;
        const int K = scan ? Kb : Kf;

        for (int step = 0; step < 512; ++step) {
            const int n = scan ? (511 - step) : step;

            // ---------- stage & compact this step's edges for our 8 graphs ----------
            if (tid < 8) eg_cnt[tid] = 0;
            __syncthreads();
            {
                const size_t eoff = (size_t)step * (size_t)K;
                for (int e = tid; e < K; e += 512) {
                    float mv = mskA[eoff + e];
                    if (mv != 0.f) {
                        int gl = gidA[eoff + e] - g0;
                        if ((unsigned)gl < 8u) {
                            int slot = atomicAdd(&eg_cnt[gl], 1);
                            if (slot < MAXE) eg_src[gl * MAXE + slot] = srcA[eoff + e];
                        }
                    }
                }
            }
            __syncthreads();

            // ---------- gather agg (warps 0-7) / load h_old (warps 8-15) ----------
            if (wid < 8) {
                const int g = wid;
                int cnt = eg_cnt[g]; if (cnt > MAXE) cnt = MAXE;
                float4 a0 = make_float4(0.f, 0.f, 0.f, 0.f);
                float4 a1 = make_float4(0.f, 0.f, 0.f, 0.f);
                for (int i = 0; i < cnt; i++) {
                    int row = eg_src[g * MAXE + i];
                    const float4* yr = (const float4*)(ybuf + (size_t)row * 256);
                    a0 = f4add(a0, __ldcg(yr + lane));
                    a1 = f4add(a1, __ldcg(yr + 32 + lane));
                }
                sm4[O_XSA + g * 68 + xslot(lane)]      = a0;
                sm4[O_XSA + g * 68 + xslot(lane + 32)] = a1;
            } else {
                const int g = wid - 8;
                const float4* hr =
                    (const float4*)(hx + ((size_t)(g0 + g) * 512 + n) * 256);
                sm4[O_XSH + g * 68 + xslot(lane)]      = __ldcg(hr + lane);
                sm4[O_XSH + g * 68 + xslot(lane + 32)] = __ldcg(hr + 32 + lane);
            }
            __syncthreads();

            // ---------- GRU GEMM: gi (rows 0-47 @ agg) / gh (rows 48-95 @ h) ----------
            {
                const int r0 = wid * 6;                       // local GRU row base
                const float4* xb = sm4 + (wid < 8 ? O_XSA : O_XSH) + gg * 68;
                float4 xr[16];
                #pragma unroll
                for (int c = 0; c < 16; c++) xr[c] = xb[c * 4 + ks];
                const float4* wb = sm4 + O_WG4 + r0 * 64;
                float acc[6];
                #pragma unroll
                for (int i = 0; i < 6; i++) acc[i] = 0.f;
                #pragma unroll
                for (int c = 0; c < 16; c++) {
                    float4 xv = xr[c];
                    #pragma unroll
                    for (int i = 0; i < 6; i++) {
                        float4 wv = wb[i * 64 + c * 4 + ks];
                        acc[i] = fmaf(wv.x, xv.x,
                                 fmaf(wv.y, xv.y,
                                 fmaf(wv.z, xv.z,
                                 fmaf(wv.w, xv.w, acc[i]))));
                    }
                }
                #pragma unroll
                for (int off = 8; off <= 16; off <<= 1)
                    #pragma unroll
                    for (int i = 0; i < 6; i++)
                        acc[i] += __shfl_xor_sync(FULLMASK, acc[i], off);
                if (lane < 8) {
                    float* ob = smf + (r0 < 48 ? F_GIS + r0 * 8
                                               : F_GHS + (r0 - 48) * 8);
                    #pragma unroll
                    for (int i = 0; i < 6; i++) ob[i * 8 + lane] = acc[i];
                }
            }
            __syncthreads();

            // ---------- gate combine -> h_new (staged) ----------
            if (tid < 128) {
                int g = tid >> 4, c = tid & 15;
                const float* gis = smf + F_GIS;
                const float* ghs = smf + F_GHS;
                float rr = gis[c * 8 + g] + smf[F_BIH + c]
                         + ghs[c * 8 + g] + smf[F_BHH + c];
                float zz = gis[(16 + c) * 8 + g] + smf[F_BIH + 16 + c]
                         + ghs[(16 + c) * 8 + g] + smf[F_BHH + 16 + c];
                float hn = ghs[(32 + c) * 8 + g] + smf[F_BHH + 32 + c];
                float in_ = gis[(32 + c) * 8 + g] + smf[F_BIH + 32 + c];
                float r = 1.f / (1.f + __expf(-rr));
                float z = 1.f / (1.f + __expf(-zz));
                float nn = tanhf(in_ + r * hn);
                int k = ch0 + c, kc = k >> 2;
                float ho = smf[(O_XSH + g * 68 + xslot(kc)) * 4 + (k & 3)];
                smf[F_HST + g * 16 + c] = (1.f - z) * nn + z * ho;
            }
            __syncthreads();
            if (tid < 32) {          // publish h_new slice (pre-barrier)
                int g = tid >> 2, q = tid & 3;
                float4 v = *(const float4*)(smf + F_HST + g * 16 + q * 4);
                __stcg((float4*)(hnew_buf + (size_t)(g0 + g) * 256 + ch0 + q * 4), v);
            }
            group_barrier(gb);       // h_new complete group-wide

            // ---------- commit hx + reload full h_new ----------
            if (tid < 32) {
                int g = tid >> 2, q = tid & 3;
                float4 v = *(const float4*)(smf + F_HST + g * 16 + q * 4);
                __stcg((float4*)(hx + ((size_t)(g0 + g) * 512 + n) * 256 + ch0 + q * 4), v);
            }
            {
                int g = tid >> 6, kc = tid & 63;
                float4 v = __ldcg((const float4*)(hnew_buf + (size_t)(g0 + g) * 256) + kc);
                sm4[O_XSH + g * 68 + xslot(kc)] = v;
            }
            __syncthreads();

            // ---------- M1: t = relu(W1 h_new + b1), 1 row per warp ----------
            {
                const float4* xb = sm4 + O_XSH + gg * 68;
                const float4* wb = sm4 + O_W14 + wid * 64;
                float acc = 0.f;
                #pragma unroll
                for (int c = 0; c < 16; c++) {
                    float4 xv = xb[c * 4 + ks];
                    float4 wv = wb[c * 4 + ks];
                    acc = fmaf(wv.x, xv.x, fmaf(wv.y, xv.y,
                          fmaf(wv.z, xv.z, fmaf(wv.w, xv.w, acc))));
                }
                acc += __shfl_xor_sync(FULLMASK, acc, 8);
                acc += __shfl_xor_sync(FULLMASK, acc, 16);
                if (lane < 8)
                    smf[F_TST + lane * 16 + wid] = fmaxf(acc + smf[F_B1 + wid], 0.f);
            }
            __syncthreads();
            if (tid < 32) {
                int g = tid >> 2, q = tid & 3;
                float4 v = *(const float4*)(smf + F_TST + g * 16 + q * 4);
                __stcg((float4*)(tbuf + (size_t)(g0 + g) * 256 + ch0 + q * 4), v);
            }
            group_barrier(gb);       // t complete group-wide

            // ---------- reload full t ----------
            {
                int g = tid >> 6, kc = tid & 63;
                float4 v = __ldcg((const float4*)(tbuf + (size_t)(g0 + g) * 256) + kc);
                sm4[O_XSA + g * 68 + xslot(kc)] = v;
            }
            __syncthreads();

            // ---------- M2: y = relu(W2 t + b2) ----------
            {
                const float4* xb = sm4 + O_XSA + gg * 68;
                const float4* wb = sm4 + O_W24 + wid * 64;
                float acc = 0.f;
                #pragma unroll
                for (int c = 0; c < 16; c++) {
                    float4 xv = xb[c * 4 + ks];
                    float4 wv = wb[c * 4 + ks];
                    acc = fmaf(wv.x, xv.x, fmaf(wv.y, xv.y,
                          fmaf(wv.z, xv.z, fmaf(wv.w, xv.w, acc))));
                }
                acc += __shfl_xor_sync(FULLMASK, acc, 8);
                acc += __shfl_xor_sync(FULLMASK, acc, 16);
                if (lane < 8)
                    smf[F_YST + lane * 16 + wid] = fmaxf(acc + smf[F_B2 + wid], 0.f);
            }
            __syncthreads();
            if (tid < 32) {
                int g = tid >> 2, q = tid & 3;
                float4 v = *(const float4*)(smf + F_YST + g * 16 + q * 4);
                __stcg((float4*)(ybuf + ((size_t)(g0 + g) * 512 + n) * 256 + ch0 + q * 4), v);
            }
            group_barrier(gb);       // y complete -> next step may gather
        }
    }
}

extern "C" void kernel_launch(void* const* d_in, const int* in_sizes, int n_in,
                              void* d_out, int out_size) {
    const float* x    = (const float*)d_in[0];
    const float* W1   = (const float*)d_in[1];
    const float* b1   = (const float*)d_in[2];
    const float* W2   = (const float*)d_in[3];
    const float* b2   = (const float*)d_in[4];
    const float* w_ih = (const float*)d_in[5];
    const float* b_ih = (const float*)d_in[6];
    const float* w_hh = (const float*)d_in[7];
    const float* b_hh = (const float*)d_in[8];
    const int*   src_f = (const int*)d_in[9];
    const int*   gid_f = (const int*)d_in[10];
    const float* msk_f = (const float*)d_in[11];
    const int*   src_b = (const int*)d_in[12];
    const int*   gid_b = (const int*)d_in[13];
    const float* msk_b = (const float*)d_in[14];
    float* hx = (float*)d_out;

    int Kf = in_sizes[9] / 512;
    int Kb = in_sizes[12] / 512;

    cudaMemcpyAsync(hx, x, (size_t)32768 * 256 * sizeof(float),
                    cudaMemcpyDeviceToDevice);

    cudaFuncSetAttribute(gnn_kernel, cudaFuncAttributeMaxDynamicSharedMemorySize,
                         SMEM_BYTES);
    gnn_kernel<<<128, 512, SMEM_BYTES>>>(hx, W1, b1, W2, b2, w_ih, b_ih, w_hh, b_hh,
                                         src_f, gid_f, msk_f, src_b, gid_b, msk_b,
                                         Kf, Kb);
}